// round 15
// baseline (speedup 1.0000x reference)
#include <cuda_runtime.h>
#include <cuda_fp16.h>
#include <cstdint>
#include <cstring>

#define Bv 4
#define Nv 256
#define Dv 256
#define Mv (Bv*Nv*Nv)     // 262144 pair rows
#define BIv (Bv*Nv)       // 1024 (b,i) rows

// scratch (no allocations allowed)
__device__ __align__(16) float g_s12[BIv * 512];     // s1 (cols 0..255), s2+b_in (cols 256..511)
__device__ __align__(16) float g_part[4096 * 256];   // per-CTA weighted column partials
__device__ __align__(16) float g_zpart[4096];        // per-CTA exp-sum partials
__device__ int g_s12_done;                            // s12 arrival counter
// W_in[512:768,:] fp16, layout [c32][kg16][n][16perm]
__device__ __align__(16) __half g_w3h[256 * 256];

__device__ __forceinline__ uint32_t smem_u32(const void* p) {
    uint32_t a;
    asm("{ .reg .u64 t; cvta.to.shared.u64 t, %1; cvt.u32.u64 %0, t; }" : "=r"(a) : "l"(p));
    return a;
}
__device__ __forceinline__ uint32_t f2h2(float a, float b) {
    __half2 h = __floats2half2_rn(a, b);
    uint32_t u; memcpy(&u, &h, 4); return u;
}
__device__ __forceinline__ void mma_f16(float* d, const uint32_t* a, const uint32_t* b) {
    asm volatile(
        "mma.sync.aligned.m16n8k16.row.col.f32.f16.f16.f32 "
        "{%0,%1,%2,%3}, {%4,%5,%6,%7}, {%8,%9}, {%0,%1,%2,%3};"
        : "+f"(d[0]), "+f"(d[1]), "+f"(d[2]), "+f"(d[3])
        : "r"(a[0]), "r"(a[1]), "r"(a[2]), "r"(a[3]), "r"(b[0]), "r"(b[1]));
}
__device__ __forceinline__ void ldsm4(uint32_t* r, uint32_t addr) {
    asm volatile("ldmatrix.sync.aligned.m8n8.x4.shared.b16 {%0,%1,%2,%3}, [%4];"
        : "=r"(r[0]), "=r"(r[1]), "=r"(r[2]), "=r"(r[3]) : "r"(addr));
}
#define CP_ASYNC16(s, g) \
    asm volatile("cp.async.ca.shared.global [%0], [%1], 16;" :: "r"(s), "l"(g))
#define CP_COMMIT()  asm volatile("cp.async.commit_group;" ::: "memory")
#define CP_WAIT1()   asm volatile("cp.async.wait_group 1;" ::: "memory")

// ===========================================================================
// k_prep: fp16 permuted copy of W_in[512:768,:]; resets s12 counter.
__global__ void k_prep(const float* __restrict__ Win) {
    int k = blockIdx.x, n = threadIdx.x;
    if (k == 0 && n == 0) g_s12_done = 0;
    int c = k >> 5, kg = (k >> 4) & 1, kk = k & 15;
    int t = (kk & 7) >> 1;
    int u = (kk & 1) + ((kk >> 3) << 1);
    int p = t * 4 + u;
    g_w3h[(((size_t)(c * 2 + kg)) * 256 + n) * 16 + p] =
        __float2half_rn(Win[(size_t)(512 + k) * 256 + n]);
}

// ===========================================================================
// k_main, grid 4224:
//   blocks 0..127   -> s12 GEMM (nodes @ W_in[0:512] -> g_s12) + counter arrive
//   blocks 128..4223 -> fp16 mma GEMM; epilogue spin-waits for s12 completion.
#define A_STG_B 5120                     // 64 rows x 80B
#define B_STG_B 16384                    // 32k x 256n x 2B
#define TSTR    264                      // epilogue tile stride (floats)
#define OFF_A    0                       // 2 stages: 10240
#define OFF_B    10240                   // union: 3 B stages (49152) / tile (67584)
#define OFF_S1   77824
#define OFF_WC   78848
#define OFF_RED  79872                   // 64*4 floats
#define OFF_WROW 80896                   // 64 floats
#define SMEM_MAIN_BYTES 81152

__global__ void __launch_bounds__(256, 2) k_main(const float* __restrict__ edges,
                                                 const float* __restrict__ Wcoef,
                                                 const float* __restrict__ aux,
                                                 const float* __restrict__ bcoef,
                                                 const float* __restrict__ nodes,
                                                 const float* __restrict__ Win,
                                                 const float* __restrict__ b_in,
                                                 float* __restrict__ cat) {
    extern __shared__ __align__(128) char smc[];
    int tid = threadIdx.x;

    if (blockIdx.x < 128) {
        // ---- s12 GEMM: BM=64 x BN=64 x BK=16, 2-stage cp.async (R11 code)
        float* As = (float*)smc;                       // 2 x 64*20
        float* Bs = (float*)(smc + 10240);             // 2 x 16*68
        int bx = blockIdx.x;
        int tx = tid & 15, ty = tid >> 4;
        int row0 = (bx & 15) * 64;
        int n0   = (bx >> 4) * 64;

        int arr = tid >> 2, aseg = tid & 3;
        uint32_t a_dst = smem_u32(As) + (uint32_t)(arr * 20 + aseg * 4) * 4;
        const float* a_src = &nodes[(size_t)(row0 + arr) * 256 + aseg * 4];
        int bk = tid >> 4, bnq = tid & 15;
        int nn = n0 + bnq * 4;
        uint32_t b_dst = smem_u32(Bs) + (uint32_t)(bk * 68 + bnq * 4) * 4;
        const float* b_src = (nn < 256) ? &Win[(size_t)bk * 256 + nn]
                                        : &Win[(size_t)(256 + bk) * 256 + (nn - 256)];
        const uint32_t A_STG = 64 * 20 * 4;
        const uint32_t B_STG = 16 * 68 * 4;

        CP_ASYNC16(a_dst, (const void*)a_src);
        CP_ASYNC16(b_dst, (const void*)b_src);
        CP_COMMIT();
        CP_ASYNC16(a_dst + A_STG, (const void*)(a_src + 16));
        CP_ASYNC16(b_dst + B_STG, (const void*)(b_src + 16 * 256));
        CP_COMMIT();

        float c[4][4] = {};
        for (int ch = 0; ch < 16; ch++) {
            int s = ch & 1;
            CP_WAIT1();
            __syncthreads();
            const float* as = As + s * (64 * 20);
            const float* bs = Bs + s * (16 * 68);
#pragma unroll
            for (int k = 0; k < 16; k++) {
                float a[4], bb[4];
#pragma unroll
                for (int i = 0; i < 4; i++) a[i] = as[(ty * 4 + i) * 20 + k];
                *(float4*)bb = *(const float4*)&bs[k * 68 + tx * 4];
#pragma unroll
                for (int i = 0; i < 4; i++)
#pragma unroll
                    for (int j = 0; j < 4; j++) c[i][j] += a[i] * bb[j];
            }
            __syncthreads();
            if (ch + 2 < 16) {
                int k0 = (ch + 2) * 16;
                CP_ASYNC16(a_dst + s * A_STG, (const void*)(a_src + k0));
                CP_ASYNC16(b_dst + s * B_STG, (const void*)(b_src + (size_t)k0 * 256));
            }
            CP_COMMIT();
        }
#pragma unroll
        for (int i = 0; i < 4; i++) {
            int row = row0 + ty * 4 + i;
#pragma unroll
            for (int j = 0; j < 4; j++) {
                int n = n0 + tx * 4 + j;
                float v = c[i][j] + (n >= 256 ? b_in[n - 256] : 0.f);
                g_s12[(size_t)row * 512 + n] = v;
            }
        }
        __threadfence();
        __syncthreads();
        if (tid == 0) atomicAdd(&g_s12_done, 1);
        return;
    }

    // ---- main GEMM block
    float* s1s  = (float*)(smc + OFF_S1);
    float* wcs  = (float*)(smc + OFF_WC);
    float* red  = (float*)(smc + OFF_RED);
    float* wrow = (float*)(smc + OFF_WROW);
    float* tile = (float*)(smc + OFF_B);   // valid after mainloop (B stages dead)

    int lane = tid & 31, wid = tid >> 5;
    int gid = lane >> 2, tig = lane & 3;
    int wm = wid & 1, wn = wid >> 1;
    int m0w = wm * 32, n0w = wn * 64;

    int mb = blockIdx.x - 128;
    int row0 = mb * 64;
    int bi = row0 >> 8;
    int b  = bi >> 8;

    wcs[tid] = Wcoef[tid];

    int ar = tid >> 2, aj = tid & 3;
    const float* a_src = &edges[(size_t)(row0 + ar) * 256 + aj * 8];
    uint32_t a_sts = smem_u32(smc + OFF_A) + (uint32_t)(ar * 80 + aj * 16);

    uint32_t b_smem = smem_u32(smc + OFF_B);
    const char* b_gbase = (const char*)g_w3h;

    float4 rb[2][2];
    int lrow = ((lane >> 3) & 1) * 8 + (lane & 7);
    int lkb  = (lane >> 4) * 16;

#define LDGA(c, bf) do { \
        rb[bf][0] = *(const float4*)(a_src + (c) * 32); \
        rb[bf][1] = *(const float4*)(a_src + (c) * 32 + 4); } while (0)
#define STSA(c, bf) do { \
        uint4 t_; \
        t_.x = f2h2(rb[bf][0].x, rb[bf][0].y); \
        t_.y = f2h2(rb[bf][0].z, rb[bf][0].w); \
        t_.z = f2h2(rb[bf][1].x, rb[bf][1].y); \
        t_.w = f2h2(rb[bf][1].z, rb[bf][1].w); \
        asm volatile("st.shared.v4.b32 [%0], {%1,%2,%3,%4};" \
            :: "r"(a_sts + ((c) & 1) * A_STG_B), "r"(t_.x), "r"(t_.y), "r"(t_.z), "r"(t_.w) \
            : "memory"); } while (0)
#define CPB(c) do { \
        int s3_ = (c) - ((c) / 3) * 3; \
        _Pragma("unroll") \
        for (int i_ = 0; i_ < 4; i_++) { \
            int u_ = tid + i_ * 256; \
            int kg_ = u_ >> 9, n_ = (u_ >> 1) & 255, h_ = u_ & 1; \
            uint32_t d_ = b_smem + s3_ * B_STG_B + kg_ * 8192 + n_ * 32 + h_ * 16; \
            const void* s_ = b_gbase + (((size_t)((c) * 2 + kg_)) * 256 + n_) * 32 + h_ * 16; \
            CP_ASYNC16(d_, s_); \
        } } while (0)

    // ---- prologue
    LDGA(0, 0); LDGA(1, 1);
    CPB(0); CP_COMMIT();
    CPB(1); CP_COMMIT();
    STSA(0, 0);
    CP_WAIT1();
    __syncthreads();

    float acc[2][8][4] = {};

#pragma unroll
    for (int c = 0; c < 8; c++) {
        if (c + 2 < 8) CPB(c + 2);
        CP_COMMIT();
        if (c + 1 < 8) STSA(c + 1, (c + 1) & 1);
        if (c + 2 < 8) LDGA(c + 2, c & 1);

        uint32_t aBase = smem_u32(smc + OFF_A) + (c & 1) * A_STG_B;
        const char* Bs_ = smc + OFF_B + (c - (c / 3) * 3) * B_STG_B;
#pragma unroll
        for (int ks = 0; ks < 2; ks++) {
            uint32_t a[2][4];
#pragma unroll
            for (int mf = 0; mf < 2; mf++)
                ldsm4(a[mf], aBase + (uint32_t)((m0w + mf * 16 + lrow) * 80 + ks * 32 + lkb));
            uint32_t bf[8][2];
#pragma unroll
            for (int nf = 0; nf < 8; nf++) {
                int n = n0w + nf * 8 + gid;
                uint2 pv = *(const uint2*)(Bs_ + ks * 8192 + n * 32 + tig * 8);
                bf[nf][0] = pv.x; bf[nf][1] = pv.y;
            }
#pragma unroll
            for (int mf = 0; mf < 2; mf++)
#pragma unroll
                for (int nf = 0; nf < 8; nf++)
                    mma_f16(acc[mf][nf], a[mf], bf[nf]);
        }
        CP_WAIT1();
        __syncthreads();
    }

    // ---- wait for s12 producers, then stage s1
    if (tid == 0) {
        while (*(volatile int*)&g_s12_done < 128) { }
    }
    __syncthreads();
    __threadfence();
    s1s[tid] = g_s12[(size_t)bi * 512 + tid];
    __syncthreads();

    // ---- epilogue 1: add s1/s2, relu, store TILE only, coef partials
#pragma unroll
    for (int mf = 0; mf < 2; mf++) {
#pragma unroll
        for (int rr = 0; rr < 2; rr++) {
            int row_local = m0w + mf * 16 + gid + rr * 8;
            int jj = (row0 & 255) + row_local;
            const float* s2p = &g_s12[((size_t)(b * 256 + jj)) * 512 + 256];
            float* tilep = &tile[(size_t)row_local * TSTR];
            float csum = 0.f;
#pragma unroll
            for (int nf = 0; nf < 8; nf++) {
                int nl = n0w + nf * 8 + tig * 2;
                float v0 = acc[mf][nf][rr*2]   + s1s[nl]   + s2p[nl];
                float v1 = acc[mf][nf][rr*2+1] + s1s[nl+1] + s2p[nl+1];
                v0 = fmaxf(v0, 0.f); v1 = fmaxf(v1, 0.f);
                csum += v0 * wcs[nl] + v1 * wcs[nl + 1];
                float2 st = { v0, v1 };
                *(float2*)&tilep[nl] = st;
            }
            csum += __shfl_xor_sync(0xffffffffu, csum, 1);
            csum += __shfl_xor_sync(0xffffffffu, csum, 2);
            if (tig == 0) red[row_local * 4 + wn] = csum;
        }
    }
    __syncthreads();

    // ---- epilogue 1.5: coalesced cat store from tile (16 x float4/thread)
    {
        float* catbase = &cat[(size_t)row0 * 256];
#pragma unroll
        for (int i = 0; i < 16; i++) {
            int idx = i * 1024 + tid * 4;
            int row = idx >> 8, col = idx & 255;
            float4 v = *(const float4*)&tile[(size_t)row * TSTR + col];
            *(float4*)&catbase[(size_t)row * 256 + col] = v;
        }
    }

    // ---- epilogue 2: w_j = exp(aux + coef + bc)
    if (tid < 64) {
        float coef = red[tid*4] + red[tid*4+1] + red[tid*4+2] + red[tid*4+3];
        wrow[tid] = __expf(aux[(size_t)row0 + tid] + coef + bcoef[0]);
    }
    __syncthreads();
    if (tid == 0) {
        float z = 0.f;
#pragma unroll
        for (int j = 0; j < 64; j++) z += wrow[j];
        g_zpart[mb] = z;
    }

    // ---- epilogue 3: weighted column sums from the smem tile
    {
        float S = 0.f;
#pragma unroll 8
        for (int j = 0; j < 64; j++) S += wrow[j] * tile[(size_t)j * TSTR + tid];
        g_part[(size_t)mb * 256 + tid] = S;
    }
}

// ===========================================================================
// k_out (fused reduce): resid rows computed in smem from g_part/g_zpart, then
// nodes + relu(resid @ W_out + b_out). BM=32 BN=64, grid (32,4).
__global__ void k_out(const float* __restrict__ nodes, const float* __restrict__ Wout,
                      const float* __restrict__ b_out, float* __restrict__ outn) {
    __shared__ float rs[32 * 256];        // resid rows [row][d]
    __shared__ float rz[32];
    __shared__ float Bs[16][64];
    int tid = threadIdx.x;
    int tx = tid & 15, ty = tid >> 4;
    int row0 = blockIdx.x * 32;
    int n0   = blockIdx.y * 64;

    if (tid < 32) {
        int q0 = (row0 + tid) * 4;
        float z = g_zpart[q0] + g_zpart[q0+1] + g_zpart[q0+2] + g_zpart[q0+3];
        rz[tid] = 1.f / z;
    }
    __syncthreads();
#pragma unroll 4
    for (int r = 0; r < 32; r++) {
        size_t q0 = (size_t)(row0 + r) * 4 * 256 + tid;
        float s = g_part[q0] + g_part[q0 + 256] + g_part[q0 + 512] + g_part[q0 + 768];
        rs[r * 256 + tid] = s * rz[r];
    }
    __syncthreads();

    float c[2][4] = {};
    for (int k0 = 0; k0 < 256; k0 += 16) {
        {
            int k = tid >> 4, nq = tid & 15;
            *(float4*)&Bs[k][nq*4] = *(const float4*)&Wout[(size_t)(k0 + k) * 256 + n0 + nq * 4];
        }
        __syncthreads();
#pragma unroll
        for (int k = 0; k < 16; k++) {
            float a0 = rs[(ty*2) * 256 + k0 + k];
            float a1 = rs[(ty*2+1) * 256 + k0 + k];
            float bb[4];
            *(float4*)bb = *(float4*)&Bs[k][tx*4];
#pragma unroll
            for (int j = 0; j < 4; j++) { c[0][j] += a0 * bb[j]; c[1][j] += a1 * bb[j]; }
        }
        __syncthreads();
    }
#pragma unroll
    for (int i = 0; i < 2; i++) {
        int row = row0 + ty*2 + i;
#pragma unroll
        for (int j = 0; j < 4; j++) {
            int n = n0 + tx*4 + j;
            float v = fmaxf(c[i][j] + b_out[n], 0.f);
            outn[(size_t)row * 256 + n] = nodes[(size_t)row * 256 + n] + v;
        }
    }
}

// ===========================================================================
extern "C" void kernel_launch(void* const* d_in, const int* in_sizes, int n_in,
                              void* d_out, int out_size) {
    const float* nodes = (const float*)d_in[0];
    const float* edges = (const float*)d_in[1];
    const float* aux   = (const float*)d_in[2];
    // d_in[3] = nums (unused)
    const float* Win   = (const float*)d_in[4];
    const float* b_in  = (const float*)d_in[5];
    const float* Wcoef = (const float*)d_in[6];
    const float* bcoef = (const float*)d_in[7];
    const float* Wout  = (const float*)d_in[8];
    const float* b_out = (const float*)d_in[9];

    float* out_nodes = (float*)d_out;                    // [4,256,256]
    float* out_cat   = out_nodes + (size_t)BIv * Dv;     // [4,256,256,256]

    cudaFuncSetAttribute(k_main, cudaFuncAttributeMaxDynamicSharedMemorySize,
                         SMEM_MAIN_BYTES);

    k_prep<<<256, 256>>>(Win);
    k_main<<<4224, 256, SMEM_MAIN_BYTES>>>(edges, Wcoef, aux, bcoef,
                                           nodes, Win, b_in, out_cat);
    k_out <<<dim3(32, 4), 256>>>(nodes, Wout, b_out, out_nodes);
}

// round 16
// speedup vs baseline: 1.0549x; 1.0549x over previous
#include <cuda_runtime.h>
#include <cuda_fp16.h>
#include <cstdint>
#include <cstring>

#define Bv 4
#define Nv 256
#define Dv 256
#define Mv (Bv*Nv*Nv)     // 262144 pair rows
#define BIv (Bv*Nv)       // 1024 (b,i) rows

// scratch (no allocations allowed)
__device__ __align__(16) float g_s12[BIv * 512];     // s1 (cols 0..255), s2+b_in (cols 256..511)
__device__ __align__(16) float g_part[4096 * 256];   // per-CTA weighted column partials
__device__ __align__(16) float g_zpart[4096];        // per-CTA exp-sum partials
// W_in[512:768,:] fp16, layout [c32][kg16][n][16perm]
__device__ __align__(16) __half g_w3h[256 * 256];

__device__ __forceinline__ uint32_t smem_u32(const void* p) {
    uint32_t a;
    asm("{ .reg .u64 t; cvta.to.shared.u64 t, %1; cvt.u32.u64 %0, t; }" : "=r"(a) : "l"(p));
    return a;
}
__device__ __forceinline__ uint32_t f2h2(float a, float b) {
    __half2 h = __floats2half2_rn(a, b);
    uint32_t u; memcpy(&u, &h, 4); return u;
}
__device__ __forceinline__ void mma_f16(float* d, const uint32_t* a, const uint32_t* b) {
    asm volatile(
        "mma.sync.aligned.m16n8k16.row.col.f32.f16.f16.f32 "
        "{%0,%1,%2,%3}, {%4,%5,%6,%7}, {%8,%9}, {%0,%1,%2,%3};"
        : "+f"(d[0]), "+f"(d[1]), "+f"(d[2]), "+f"(d[3])
        : "r"(a[0]), "r"(a[1]), "r"(a[2]), "r"(a[3]), "r"(b[0]), "r"(b[1]));
}
__device__ __forceinline__ void ldsm4(uint32_t* r, uint32_t addr) {
    asm volatile("ldmatrix.sync.aligned.m8n8.x4.shared.b16 {%0,%1,%2,%3}, [%4];"
        : "=r"(r[0]), "=r"(r[1]), "=r"(r[2]), "=r"(r[3]) : "r"(addr));
}
#define CP_ASYNC16(s, g) \
    asm volatile("cp.async.ca.shared.global [%0], [%1], 16;" :: "r"(s), "l"(g))
#define CP_COMMIT()  asm volatile("cp.async.commit_group;" ::: "memory")
#define CP_WAIT1()   asm volatile("cp.async.wait_group 1;" ::: "memory")

// ===========================================================================
// k_prep_s12: blocks 0..255 -> fp16 permuted copy of W_in[512:768,:];
//             blocks 256..383 -> s12 GEMM, BK=64 (4 chunks), k-major As,
//             register double-buffered LDG->STS for both operands.
#define P_STG 4352                        // 64 k x 68 pad floats per stage
__global__ void k_prep_s12(const float* __restrict__ nodes, const float* __restrict__ Win,
                           const float* __restrict__ b_in) {
    int tid = threadIdx.x;
    if (blockIdx.x < 256) {
        int k = blockIdx.x, n = tid;
        int c = k >> 5, kg = (k >> 4) & 1, kk = k & 15;
        int t = (kk & 7) >> 1;
        int u = (kk & 1) + ((kk >> 3) << 1);
        int p = t * 4 + u;
        g_w3h[(((size_t)(c * 2 + kg)) * 256 + n) * 16 + p] =
            __float2half_rn(Win[(size_t)(512 + k) * 256 + n]);
        return;
    }
    // ---- s12 GEMM: BM=64 x BN=64 x BK=64, 2-stage, k-major As + Bs
    extern __shared__ __align__(16) float psm[];
    float* As = psm;                      // [st][k][row] : st*P_STG + k*68 + row
    float* Bs = psm + 2 * P_STG;          // [st][k][n]

    int bx = blockIdx.x - 256;            // 0..127
    int tx = tid & 15, ty = tid >> 4;
    int row0 = (bx & 15) * 64;
    int n0   = (bx >> 4) * 64;

    int arow = tid >> 2;                  // 0..63
    int akq  = tid & 3;                   // k-quad group
    const float* a_base = &nodes[(size_t)(row0 + arow) * 256];
    const float* WB = (n0 < 256) ? &Win[n0] : &Win[(size_t)256 * 256 + (n0 - 256)];

    float4 av[4], bv[4];
#define P_LDG(c) do { \
        _Pragma("unroll") \
        for (int i_ = 0; i_ < 4; i_++) { \
            int kq_ = akq + i_ * 4; \
            av[i_] = *(const float4*)(a_base + (c) * 64 + kq_ * 4); \
        } \
        _Pragma("unroll") \
        for (int i_ = 0; i_ < 4; i_++) { \
            int idx_ = tid + i_ * 256; int k_ = idx_ >> 4, seg_ = idx_ & 15; \
            bv[i_] = *(const float4*)(WB + ((size_t)((c) * 64 + k_)) * 256 + seg_ * 4); \
        } } while (0)
#define P_STS(st) do { \
        _Pragma("unroll") \
        for (int i_ = 0; i_ < 4; i_++) { \
            int kq_ = akq + i_ * 4; \
            float* ap_ = &As[(st) * P_STG + (kq_ * 4) * 68 + arow]; \
            ap_[0] = av[i_].x; ap_[68] = av[i_].y; ap_[136] = av[i_].z; ap_[204] = av[i_].w; \
        } \
        _Pragma("unroll") \
        for (int i_ = 0; i_ < 4; i_++) { \
            int idx_ = tid + i_ * 256; int k_ = idx_ >> 4, seg_ = idx_ & 15; \
            *(float4*)&Bs[(st) * P_STG + k_ * 68 + seg_ * 4] = bv[i_]; \
        } } while (0)

    // prologue
    P_LDG(0); P_STS(0); P_LDG(1);
    __syncthreads();

    float c[4][4] = {};
    for (int ch = 0; ch < 4; ch++) {
        int s = ch & 1;
        if (ch + 1 < 4) {
            P_STS(s ^ 1);
            if (ch + 2 < 4) P_LDG(ch + 2);
        }
        const float* as = &As[s * P_STG];
        const float* bs = &Bs[s * P_STG];
#pragma unroll 8
        for (int k = 0; k < 64; k++) {
            float a[4], bb[4];
            *(float4*)a  = *(const float4*)&as[k * 68 + ty * 4];
            *(float4*)bb = *(const float4*)&bs[k * 68 + tx * 4];
#pragma unroll
            for (int i = 0; i < 4; i++)
#pragma unroll
                for (int j = 0; j < 4; j++) c[i][j] += a[i] * bb[j];
        }
        __syncthreads();
    }
#pragma unroll
    for (int i = 0; i < 4; i++) {
        int row = row0 + ty * 4 + i;
#pragma unroll
        for (int j = 0; j < 4; j++) {
            int n = n0 + tx * 4 + j;
            float v = c[i][j] + (n >= 256 ? b_in[n - 256] : 0.f);
            g_s12[(size_t)row * 512 + n] = v;
        }
    }
}
#define SMEM_PREP_BYTES (4 * P_STG * 4)   // 69632

// ===========================================================================
// k_main: fp16 mma m16n8k16, BM=64 x BN=256 x BK=32, 256 thr.
// Epilogue: tile (smem) -> coalesced cat store; softmax partials from tile.
#define A_STG_B 5120                     // 64 rows x 80B
#define B_STG_B 16384                    // 32k x 256n x 2B
#define TSTR    264                      // epilogue tile stride (floats)
#define OFF_A    0                       // 2 stages: 10240
#define OFF_B    10240                   // union: 3 B stages (49152) / tile (67584)
#define OFF_S1   77824
#define OFF_WC   78848
#define OFF_RED  79872                   // 64*4 floats
#define OFF_WROW 80896                   // 64 floats
#define SMEM_MAIN_BYTES 81152

__global__ void __launch_bounds__(256, 2) k_main(const float* __restrict__ edges,
                                                 const float* __restrict__ Wcoef,
                                                 const float* __restrict__ aux,
                                                 const float* __restrict__ bcoef,
                                                 float* __restrict__ cat) {
    extern __shared__ __align__(128) char smc[];
    float* s1s  = (float*)(smc + OFF_S1);
    float* wcs  = (float*)(smc + OFF_WC);
    float* red  = (float*)(smc + OFF_RED);
    float* wrow = (float*)(smc + OFF_WROW);
    float* tile = (float*)(smc + OFF_B);   // valid after mainloop (B stages dead)

    int tid = threadIdx.x;
    int lane = tid & 31, wid = tid >> 5;
    int gid = lane >> 2, tig = lane & 3;
    int wm = wid & 1, wn = wid >> 1;
    int m0w = wm * 32, n0w = wn * 64;

    int row0 = blockIdx.x * 64;
    int bi = row0 >> 8;
    int b  = bi >> 8;

    s1s[tid] = g_s12[(size_t)bi * 512 + tid];
    wcs[tid] = Wcoef[tid];

    int ar = tid >> 2, aj = tid & 3;
    const float* a_src = &edges[(size_t)(row0 + ar) * 256 + aj * 8];
    uint32_t a_sts = smem_u32(smc + OFF_A) + (uint32_t)(ar * 80 + aj * 16);

    uint32_t b_smem = smem_u32(smc + OFF_B);
    const char* b_gbase = (const char*)g_w3h;

    float4 rb[2][2];
    int lrow = ((lane >> 3) & 1) * 8 + (lane & 7);
    int lkb  = (lane >> 4) * 16;

#define LDGA(c, bf) do { \
        rb[bf][0] = *(const float4*)(a_src + (c) * 32); \
        rb[bf][1] = *(const float4*)(a_src + (c) * 32 + 4); } while (0)
#define STSA(c, bf) do { \
        uint4 t_; \
        t_.x = f2h2(rb[bf][0].x, rb[bf][0].y); \
        t_.y = f2h2(rb[bf][0].z, rb[bf][0].w); \
        t_.z = f2h2(rb[bf][1].x, rb[bf][1].y); \
        t_.w = f2h2(rb[bf][1].z, rb[bf][1].w); \
        asm volatile("st.shared.v4.b32 [%0], {%1,%2,%3,%4};" \
            :: "r"(a_sts + ((c) & 1) * A_STG_B), "r"(t_.x), "r"(t_.y), "r"(t_.z), "r"(t_.w) \
            : "memory"); } while (0)
#define CPB(c) do { \
        int s3_ = (c) - ((c) / 3) * 3; \
        _Pragma("unroll") \
        for (int i_ = 0; i_ < 4; i_++) { \
            int u_ = tid + i_ * 256; \
            int kg_ = u_ >> 9, n_ = (u_ >> 1) & 255, h_ = u_ & 1; \
            uint32_t d_ = b_smem + s3_ * B_STG_B + kg_ * 8192 + n_ * 32 + h_ * 16; \
            const void* s_ = b_gbase + (((size_t)((c) * 2 + kg_)) * 256 + n_) * 32 + h_ * 16; \
            CP_ASYNC16(d_, s_); \
        } } while (0)

    // ---- prologue
    LDGA(0, 0); LDGA(1, 1);
    CPB(0); CP_COMMIT();
    CPB(1); CP_COMMIT();
    STSA(0, 0);
    CP_WAIT1();
    __syncthreads();

    float acc[2][8][4] = {};

#pragma unroll
    for (int c = 0; c < 8; c++) {
        if (c + 2 < 8) CPB(c + 2);
        CP_COMMIT();
        if (c + 1 < 8) STSA(c + 1, (c + 1) & 1);
        if (c + 2 < 8) LDGA(c + 2, c & 1);

        uint32_t aBase = smem_u32(smc + OFF_A) + (c & 1) * A_STG_B;
        const char* Bs_ = smc + OFF_B + (c - (c / 3) * 3) * B_STG_B;
#pragma unroll
        for (int ks = 0; ks < 2; ks++) {
            uint32_t a[2][4];
#pragma unroll
            for (int mf = 0; mf < 2; mf++)
                ldsm4(a[mf], aBase + (uint32_t)((m0w + mf * 16 + lrow) * 80 + ks * 32 + lkb));
            uint32_t bf[8][2];
#pragma unroll
            for (int nf = 0; nf < 8; nf++) {
                int n = n0w + nf * 8 + gid;
                uint2 pv = *(const uint2*)(Bs_ + ks * 8192 + n * 32 + tig * 8);
                bf[nf][0] = pv.x; bf[nf][1] = pv.y;
            }
#pragma unroll
            for (int mf = 0; mf < 2; mf++)
#pragma unroll
                for (int nf = 0; nf < 8; nf++)
                    mma_f16(acc[mf][nf], a[mf], bf[nf]);
        }
        CP_WAIT1();
        __syncthreads();
    }

    // ---- epilogue 1: add s1/s2, relu, store TILE only, coef partials
#pragma unroll
    for (int mf = 0; mf < 2; mf++) {
#pragma unroll
        for (int rr = 0; rr < 2; rr++) {
            int row_local = m0w + mf * 16 + gid + rr * 8;
            int jj = (row0 & 255) + row_local;
            const float* s2p = &g_s12[((size_t)(b * 256 + jj)) * 512 + 256];
            float* tilep = &tile[(size_t)row_local * TSTR];
            float csum = 0.f;
#pragma unroll
            for (int nf = 0; nf < 8; nf++) {
                int nl = n0w + nf * 8 + tig * 2;
                float v0 = acc[mf][nf][rr*2]   + s1s[nl]   + s2p[nl];
                float v1 = acc[mf][nf][rr*2+1] + s1s[nl+1] + s2p[nl+1];
                v0 = fmaxf(v0, 0.f); v1 = fmaxf(v1, 0.f);
                csum += v0 * wcs[nl] + v1 * wcs[nl + 1];
                float2 st = { v0, v1 };
                *(float2*)&tilep[nl] = st;
            }
            csum += __shfl_xor_sync(0xffffffffu, csum, 1);
            csum += __shfl_xor_sync(0xffffffffu, csum, 2);
            if (tig == 0) red[row_local * 4 + wn] = csum;
        }
    }
    __syncthreads();

    // ---- epilogue 1.5: coalesced cat store from tile (16 x float4/thread)
    {
        float* catbase = &cat[(size_t)row0 * 256];
#pragma unroll
        for (int i = 0; i < 16; i++) {
            int idx = i * 1024 + tid * 4;
            int row = idx >> 8, col = idx & 255;
            float4 v = *(const float4*)&tile[(size_t)row * TSTR + col];
            *(float4*)&catbase[(size_t)row * 256 + col] = v;
        }
    }

    // ---- epilogue 2: w_j = exp(aux + coef + bc)
    if (tid < 64) {
        float coef = red[tid*4] + red[tid*4+1] + red[tid*4+2] + red[tid*4+3];
        wrow[tid] = __expf(aux[(size_t)row0 + tid] + coef + bcoef[0]);
    }
    __syncthreads();
    if (tid == 0) {
        float z = 0.f;
#pragma unroll
        for (int j = 0; j < 64; j++) z += wrow[j];
        g_zpart[blockIdx.x] = z;
    }

    // ---- epilogue 3: weighted column sums from the smem tile
    {
        float S = 0.f;
#pragma unroll 8
        for (int j = 0; j < 64; j++) S += wrow[j] * tile[(size_t)j * TSTR + tid];
        g_part[(size_t)blockIdx.x * 256 + tid] = S;
    }
}

// ===========================================================================
// k_out (fused reduce): resid rows computed in smem from g_part/g_zpart, then
// nodes + relu(resid @ W_out + b_out). BM=32 BN=64, grid (32,4).
__global__ void k_out(const float* __restrict__ nodes, const float* __restrict__ Wout,
                      const float* __restrict__ b_out, float* __restrict__ outn) {
    __shared__ float rs[32 * 256];        // resid rows [row][d]
    __shared__ float rz[32];
    __shared__ float Bs[16][64];
    int tid = threadIdx.x;
    int tx = tid & 15, ty = tid >> 4;
    int row0 = blockIdx.x * 32;
    int n0   = blockIdx.y * 64;

    if (tid < 32) {
        int q0 = (row0 + tid) * 4;
        float z = g_zpart[q0] + g_zpart[q0+1] + g_zpart[q0+2] + g_zpart[q0+3];
        rz[tid] = 1.f / z;
    }
    __syncthreads();
#pragma unroll 4
    for (int r = 0; r < 32; r++) {
        size_t q0 = (size_t)(row0 + r) * 4 * 256 + tid;
        float s = g_part[q0] + g_part[q0 + 256] + g_part[q0 + 512] + g_part[q0 + 768];
        rs[r * 256 + tid] = s * rz[r];
    }
    __syncthreads();

    float c[2][4] = {};
    for (int k0 = 0; k0 < 256; k0 += 16) {
        {
            int k = tid >> 4, nq = tid & 15;
            *(float4*)&Bs[k][nq*4] = *(const float4*)&Wout[(size_t)(k0 + k) * 256 + n0 + nq * 4];
        }
        __syncthreads();
#pragma unroll
        for (int k = 0; k < 16; k++) {
            float a0 = rs[(ty*2) * 256 + k0 + k];
            float a1 = rs[(ty*2+1) * 256 + k0 + k];
            float bb[4];
            *(float4*)bb = *(float4*)&Bs[k][tx*4];
#pragma unroll
            for (int j = 0; j < 4; j++) { c[0][j] += a0 * bb[j]; c[1][j] += a1 * bb[j]; }
        }
        __syncthreads();
    }
#pragma unroll
    for (int i = 0; i < 2; i++) {
        int row = row0 + ty*2 + i;
#pragma unroll
        for (int j = 0; j < 4; j++) {
            int n = n0 + tx*4 + j;
            float v = fmaxf(c[i][j] + b_out[n], 0.f);
            outn[(size_t)row * 256 + n] = nodes[(size_t)row * 256 + n] + v;
        }
    }
}

// ===========================================================================
extern "C" void kernel_launch(void* const* d_in, const int* in_sizes, int n_in,
                              void* d_out, int out_size) {
    const float* nodes = (const float*)d_in[0];
    const float* edges = (const float*)d_in[1];
    const float* aux   = (const float*)d_in[2];
    // d_in[3] = nums (unused)
    const float* Win   = (const float*)d_in[4];
    const float* b_in  = (const float*)d_in[5];
    const float* Wcoef = (const float*)d_in[6];
    const float* bcoef = (const float*)d_in[7];
    const float* Wout  = (const float*)d_in[8];
    const float* b_out = (const float*)d_in[9];

    float* out_nodes = (float*)d_out;                    // [4,256,256]
    float* out_cat   = out_nodes + (size_t)BIv * Dv;     // [4,256,256,256]

    cudaFuncSetAttribute(k_prep_s12, cudaFuncAttributeMaxDynamicSharedMemorySize,
                         SMEM_PREP_BYTES);
    cudaFuncSetAttribute(k_main, cudaFuncAttributeMaxDynamicSharedMemorySize,
                         SMEM_MAIN_BYTES);

    k_prep_s12<<<384, 256, SMEM_PREP_BYTES>>>(nodes, Win, b_in);
    k_main    <<<4096, 256, SMEM_MAIN_BYTES>>>(edges, Wcoef, aux, bcoef, out_cat);
    k_out     <<<dim3(32, 4), 256>>>(nodes, Wout, b_out, out_nodes);
}

// round 17
// speedup vs baseline: 1.0886x; 1.0319x over previous
#include <cuda_runtime.h>
#include <cuda_fp16.h>
#include <cstdint>
#include <cstring>

#define Bv 4
#define Nv 256
#define Dv 256
#define Mv (Bv*Nv*Nv)     // 262144 pair rows
#define BIv (Bv*Nv)       // 1024 (b,i) rows

// scratch (no allocations allowed)
__device__ __align__(16) float g_s12[BIv * 512];     // s1 (cols 0..255), s2+b_in (cols 256..511)
__device__ __align__(16) float g_part[4096 * 256];   // per-CTA weighted column partials
__device__ __align__(16) float g_zpart[4096];        // per-CTA exp-sum partials
// ALL of W_in [768,256] fp16, permuted chunk layout: chunk cg=k>>5 (0..23),
// entry (((cg*2 + kg)*256 + n)*16 + p) with kg=(k>>4)&1, p = perm(k&15)
__device__ __align__(16) __half g_wh[768 * 256];

__device__ __forceinline__ uint32_t smem_u32(const void* p) {
    uint32_t a;
    asm("{ .reg .u64 t; cvta.to.shared.u64 t, %1; cvt.u32.u64 %0, t; }" : "=r"(a) : "l"(p));
    return a;
}
__device__ __forceinline__ uint32_t f2h2(float a, float b) {
    __half2 h = __floats2half2_rn(a, b);
    uint32_t u; memcpy(&u, &h, 4); return u;
}
__device__ __forceinline__ void mma_f16(float* d, const uint32_t* a, const uint32_t* b) {
    asm volatile(
        "mma.sync.aligned.m16n8k16.row.col.f32.f16.f16.f32 "
        "{%0,%1,%2,%3}, {%4,%5,%6,%7}, {%8,%9}, {%0,%1,%2,%3};"
        : "+f"(d[0]), "+f"(d[1]), "+f"(d[2]), "+f"(d[3])
        : "r"(a[0]), "r"(a[1]), "r"(a[2]), "r"(a[3]), "r"(b[0]), "r"(b[1]));
}
__device__ __forceinline__ void ldsm4(uint32_t* r, uint32_t addr) {
    asm volatile("ldmatrix.sync.aligned.m8n8.x4.shared.b16 {%0,%1,%2,%3}, [%4];"
        : "=r"(r[0]), "=r"(r[1]), "=r"(r[2]), "=r"(r[3]) : "r"(addr));
}
#define CP_ASYNC16(s, g) \
    asm volatile("cp.async.ca.shared.global [%0], [%1], 16;" :: "r"(s), "l"(g))
#define CP_COMMIT()  asm volatile("cp.async.commit_group;" ::: "memory")
#define CP_WAIT1()   asm volatile("cp.async.wait_group 1;" ::: "memory")

// shared tiling constants (k_main + k_s12tc)
#define A_STG_B 5120                     // 64 rows x 80B
#define B_STG_B 16384                    // 32k x 256n x 2B
#define TSTR    264                      // epilogue tile stride (floats)
#define OFF_A    0                       // 2 stages: 10240
#define OFF_B    10240                   // union: 3 B stages (49152) / tile (67584)
#define OFF_S1   77824
#define OFF_WC   78848
#define OFF_RED  79872                   // 64*4 floats
#define OFF_WROW 80896                   // 64 floats
#define SMEM_MAIN_BYTES 81152
#define SMEM_S12_BYTES  59392            // OFF_B + 3*B_STG_B

// shared mainloop macros (local names: rb, a_src, a_sts, b_smem, b_gbase, tid)
#define LDGA(c, bf) do { \
        rb[bf][0] = *(const float4*)(a_src + (c) * 32); \
        rb[bf][1] = *(const float4*)(a_src + (c) * 32 + 4); } while (0)
#define STSA(c, bf) do { \
        uint4 t_; \
        t_.x = f2h2(rb[bf][0].x, rb[bf][0].y); \
        t_.y = f2h2(rb[bf][0].z, rb[bf][0].w); \
        t_.z = f2h2(rb[bf][1].x, rb[bf][1].y); \
        t_.w = f2h2(rb[bf][1].z, rb[bf][1].w); \
        asm volatile("st.shared.v4.b32 [%0], {%1,%2,%3,%4};" \
            :: "r"(a_sts + ((c) & 1) * A_STG_B), "r"(t_.x), "r"(t_.y), "r"(t_.z), "r"(t_.w) \
            : "memory"); } while (0)
#define CPB(c) do { \
        int s3_ = (c) - ((c) / 3) * 3; \
        _Pragma("unroll") \
        for (int i_ = 0; i_ < 4; i_++) { \
            int u_ = tid + i_ * 256; \
            int kg_ = u_ >> 9, n_ = (u_ >> 1) & 255, h_ = u_ & 1; \
            uint32_t d_ = b_smem + s3_ * B_STG_B + kg_ * 8192 + n_ * 32 + h_ * 16; \
            const void* s_ = b_gbase + (((size_t)((c) * 2 + kg_)) * 256 + n_) * 32 + h_ * 16; \
            CP_ASYNC16(d_, s_); \
        } } while (0)

// ===========================================================================
// k_prep: fp16 permuted copy of ALL W_in [768,256]; 4 k-rows per block.
__global__ void k_prep(const float* __restrict__ Win) {
    int n = threadIdx.x;
#pragma unroll
    for (int r = 0; r < 4; r++) {
        int k = blockIdx.x * 4 + r;
        int c = k >> 5, kg = (k >> 4) & 1, kk = k & 15;
        int t = (kk & 7) >> 1;
        int u = (kk & 1) + ((kk >> 3) << 1);
        int p = t * 4 + u;
        g_wh[(((size_t)(c * 2 + kg)) * 256 + n) * 16 + p] =
            __float2half_rn(Win[(size_t)k * 256 + n]);
    }
}

// ===========================================================================
// k_s12tc: tensor-core s12 GEMM. grid 32: (bx&15)=M-tile of 64 nodes rows,
// (bx>>4)=column half (0: W_in[0:256] cols, 1: W_in[256:512] cols + b_in).
__global__ void __launch_bounds__(256, 2) k_s12tc(const float* __restrict__ nodes,
                                                  const float* __restrict__ b_in) {
    extern __shared__ __align__(128) char smc[];
    int tid = threadIdx.x;
    int lane = tid & 31, wid = tid >> 5;
    int gid = lane >> 2, tig = lane & 3;
    int wm = wid & 1, wn = wid >> 1;
    int m0w = wm * 32, n0w = wn * 64;

    int row0 = (blockIdx.x & 15) * 64;
    int half = blockIdx.x >> 4;

    int ar = tid >> 2, aj = tid & 3;
    const float* a_src = &nodes[(size_t)(row0 + ar) * 256 + aj * 8];
    uint32_t a_sts = smem_u32(smc + OFF_A) + (uint32_t)(ar * 80 + aj * 16);
    uint32_t b_smem = smem_u32(smc + OFF_B);
    const char* b_gbase = (const char*)g_wh + (size_t)half * 8 * 16384;  // chunks half*8..+8

    float4 rb[2][2];
    int lrow = ((lane >> 3) & 1) * 8 + (lane & 7);
    int lkb  = (lane >> 4) * 16;

    LDGA(0, 0); LDGA(1, 1);
    CPB(0); CP_COMMIT();
    CPB(1); CP_COMMIT();
    STSA(0, 0);
    CP_WAIT1();
    __syncthreads();

    float acc[2][8][4] = {};
#pragma unroll
    for (int c = 0; c < 8; c++) {
        if (c + 2 < 8) CPB(c + 2);
        CP_COMMIT();
        if (c + 1 < 8) STSA(c + 1, (c + 1) & 1);
        if (c + 2 < 8) LDGA(c + 2, c & 1);
        uint32_t aBase = smem_u32(smc + OFF_A) + (c & 1) * A_STG_B;
        const char* Bs_ = smc + OFF_B + (c - (c / 3) * 3) * B_STG_B;
#pragma unroll
        for (int ks = 0; ks < 2; ks++) {
            uint32_t a[2][4];
#pragma unroll
            for (int mf = 0; mf < 2; mf++)
                ldsm4(a[mf], aBase + (uint32_t)((m0w + mf * 16 + lrow) * 80 + ks * 32 + lkb));
            uint32_t bf[8][2];
#pragma unroll
            for (int nf = 0; nf < 8; nf++) {
                int n = n0w + nf * 8 + gid;
                uint2 pv = *(const uint2*)(Bs_ + ks * 8192 + n * 32 + tig * 8);
                bf[nf][0] = pv.x; bf[nf][1] = pv.y;
            }
#pragma unroll
            for (int mf = 0; mf < 2; mf++)
#pragma unroll
                for (int nf = 0; nf < 8; nf++)
                    mma_f16(acc[mf][nf], a[mf], bf[nf]);
        }
        CP_WAIT1();
        __syncthreads();
    }

    // epilogue: optional bias, fp32 store to g_s12[row][half*256 + n]
#pragma unroll
    for (int mf = 0; mf < 2; mf++) {
#pragma unroll
        for (int rr = 0; rr < 2; rr++) {
            int row = row0 + m0w + mf * 16 + gid + rr * 8;
            float* dst = &g_s12[(size_t)row * 512 + half * 256];
#pragma unroll
            for (int nf = 0; nf < 8; nf++) {
                int nl = n0w + nf * 8 + tig * 2;
                float b0 = half ? b_in[nl] : 0.f;
                float b1 = half ? b_in[nl + 1] : 0.f;
                float2 st = { acc[mf][nf][rr*2] + b0, acc[mf][nf][rr*2+1] + b1 };
                *(float2*)&dst[nl] = st;
            }
        }
    }
}

// ===========================================================================
// k_main: fp16 mma m16n8k16, BM=64 x BN=256 x BK=32, 256 thr.
// Epilogue: tile (smem) -> coalesced cat store; softmax partials from tile.
__global__ void __launch_bounds__(256, 2) k_main(const float* __restrict__ edges,
                                                 const float* __restrict__ Wcoef,
                                                 const float* __restrict__ aux,
                                                 const float* __restrict__ bcoef,
                                                 float* __restrict__ cat) {
    extern __shared__ __align__(128) char smc[];
    float* s1s  = (float*)(smc + OFF_S1);
    float* wcs  = (float*)(smc + OFF_WC);
    float* red  = (float*)(smc + OFF_RED);
    float* wrow = (float*)(smc + OFF_WROW);
    float* tile = (float*)(smc + OFF_B);   // valid after mainloop (B stages dead)

    int tid = threadIdx.x;
    int lane = tid & 31, wid = tid >> 5;
    int gid = lane >> 2, tig = lane & 3;
    int wm = wid & 1, wn = wid >> 1;
    int m0w = wm * 32, n0w = wn * 64;

    int row0 = blockIdx.x * 64;
    int bi = row0 >> 8;
    int b  = bi >> 8;

    s1s[tid] = g_s12[(size_t)bi * 512 + tid];
    wcs[tid] = Wcoef[tid];

    int ar = tid >> 2, aj = tid & 3;
    const float* a_src = &edges[(size_t)(row0 + ar) * 256 + aj * 8];
    uint32_t a_sts = smem_u32(smc + OFF_A) + (uint32_t)(ar * 80 + aj * 16);

    uint32_t b_smem = smem_u32(smc + OFF_B);
    const char* b_gbase = (const char*)g_wh + (size_t)16 * 16384;  // chunks 16..23 = W3

    float4 rb[2][2];
    int lrow = ((lane >> 3) & 1) * 8 + (lane & 7);
    int lkb  = (lane >> 4) * 16;

    // ---- prologue
    LDGA(0, 0); LDGA(1, 1);
    CPB(0); CP_COMMIT();
    CPB(1); CP_COMMIT();
    STSA(0, 0);
    CP_WAIT1();
    __syncthreads();

    float acc[2][8][4] = {};

#pragma unroll
    for (int c = 0; c < 8; c++) {
        if (c + 2 < 8) CPB(c + 2);
        CP_COMMIT();
        if (c + 1 < 8) STSA(c + 1, (c + 1) & 1);
        if (c + 2 < 8) LDGA(c + 2, c & 1);

        uint32_t aBase = smem_u32(smc + OFF_A) + (c & 1) * A_STG_B;
        const char* Bs_ = smc + OFF_B + (c - (c / 3) * 3) * B_STG_B;
#pragma unroll
        for (int ks = 0; ks < 2; ks++) {
            uint32_t a[2][4];
#pragma unroll
            for (int mf = 0; mf < 2; mf++)
                ldsm4(a[mf], aBase + (uint32_t)((m0w + mf * 16 + lrow) * 80 + ks * 32 + lkb));
            uint32_t bf[8][2];
#pragma unroll
            for (int nf = 0; nf < 8; nf++) {
                int n = n0w + nf * 8 + gid;
                uint2 pv = *(const uint2*)(Bs_ + ks * 8192 + n * 32 + tig * 8);
                bf[nf][0] = pv.x; bf[nf][1] = pv.y;
            }
#pragma unroll
            for (int mf = 0; mf < 2; mf++)
#pragma unroll
                for (int nf = 0; nf < 8; nf++)
                    mma_f16(acc[mf][nf], a[mf], bf[nf]);
        }
        CP_WAIT1();
        __syncthreads();
    }

    // ---- epilogue 1: add s1/s2, relu, store TILE only, coef partials
#pragma unroll
    for (int mf = 0; mf < 2; mf++) {
#pragma unroll
        for (int rr = 0; rr < 2; rr++) {
            int row_local = m0w + mf * 16 + gid + rr * 8;
            int jj = (row0 & 255) + row_local;
            const float* s2p = &g_s12[((size_t)(b * 256 + jj)) * 512 + 256];
            float* tilep = &tile[(size_t)row_local * TSTR];
            float csum = 0.f;
#pragma unroll
            for (int nf = 0; nf < 8; nf++) {
                int nl = n0w + nf * 8 + tig * 2;
                float v0 = acc[mf][nf][rr*2]   + s1s[nl]   + s2p[nl];
                float v1 = acc[mf][nf][rr*2+1] + s1s[nl+1] + s2p[nl+1];
                v0 = fmaxf(v0, 0.f); v1 = fmaxf(v1, 0.f);
                csum += v0 * wcs[nl] + v1 * wcs[nl + 1];
                float2 st = { v0, v1 };
                *(float2*)&tilep[nl] = st;
            }
            csum += __shfl_xor_sync(0xffffffffu, csum, 1);
            csum += __shfl_xor_sync(0xffffffffu, csum, 2);
            if (tig == 0) red[row_local * 4 + wn] = csum;
        }
    }
    __syncthreads();

    // ---- epilogue 1.5: coalesced cat store from tile (16 x float4/thread)
    {
        float* catbase = &cat[(size_t)row0 * 256];
#pragma unroll
        for (int i = 0; i < 16; i++) {
            int idx = i * 1024 + tid * 4;
            int row = idx >> 8, col = idx & 255;
            float4 v = *(const float4*)&tile[(size_t)row * TSTR + col];
            *(float4*)&catbase[(size_t)row * 256 + col] = v;
        }
    }

    // ---- epilogue 2: w_j = exp(aux + coef + bc)
    if (tid < 64) {
        float coef = red[tid*4] + red[tid*4+1] + red[tid*4+2] + red[tid*4+3];
        wrow[tid] = __expf(aux[(size_t)row0 + tid] + coef + bcoef[0]);
    }
    __syncthreads();
    if (tid == 0) {
        float z = 0.f;
#pragma unroll
        for (int j = 0; j < 64; j++) z += wrow[j];
        g_zpart[blockIdx.x] = z;
    }

    // ---- epilogue 3: weighted column sums from the smem tile
    {
        float S = 0.f;
#pragma unroll 8
        for (int j = 0; j < 64; j++) S += wrow[j] * tile[(size_t)j * TSTR + tid];
        g_part[(size_t)blockIdx.x * 256 + tid] = S;
    }
}

// ===========================================================================
// k_out (fused reduce): resid rows computed in smem from g_part/g_zpart, then
// nodes + relu(resid @ W_out + b_out). BM=32 BN=64, grid (32,4).
__global__ void k_out(const float* __restrict__ nodes, const float* __restrict__ Wout,
                      const float* __restrict__ b_out, float* __restrict__ outn) {
    __shared__ float rs[32 * 256];        // resid rows [row][d]
    __shared__ float rz[32];
    __shared__ float Bs[16][64];
    int tid = threadIdx.x;
    int tx = tid & 15, ty = tid >> 4;
    int row0 = blockIdx.x * 32;
    int n0   = blockIdx.y * 64;

    if (tid < 32) {
        int q0 = (row0 + tid) * 4;
        float z = g_zpart[q0] + g_zpart[q0+1] + g_zpart[q0+2] + g_zpart[q0+3];
        rz[tid] = 1.f / z;
    }
    __syncthreads();
#pragma unroll 4
    for (int r = 0; r < 32; r++) {
        size_t q0 = (size_t)(row0 + r) * 4 * 256 + tid;
        float s = g_part[q0] + g_part[q0 + 256] + g_part[q0 + 512] + g_part[q0 + 768];
        rs[r * 256 + tid] = s * rz[r];
    }
    __syncthreads();

    float c[2][4] = {};
    for (int k0 = 0; k0 < 256; k0 += 16) {
        {
            int k = tid >> 4, nq = tid & 15;
            *(float4*)&Bs[k][nq*4] = *(const float4*)&Wout[(size_t)(k0 + k) * 256 + n0 + nq * 4];
        }
        __syncthreads();
#pragma unroll
        for (int k = 0; k < 16; k++) {
            float a0 = rs[(ty*2) * 256 + k0 + k];
            float a1 = rs[(ty*2+1) * 256 + k0 + k];
            float bb[4];
            *(float4*)bb = *(float4*)&Bs[k][tx*4];
#pragma unroll
            for (int j = 0; j < 4; j++) { c[0][j] += a0 * bb[j]; c[1][j] += a1 * bb[j]; }
        }
        __syncthreads();
    }
#pragma unroll
    for (int i = 0; i < 2; i++) {
        int row = row0 + ty*2 + i;
#pragma unroll
        for (int j = 0; j < 4; j++) {
            int n = n0 + tx*4 + j;
            float v = fmaxf(c[i][j] + b_out[n], 0.f);
            outn[(size_t)row * 256 + n] = nodes[(size_t)row * 256 + n] + v;
        }
    }
}

// ===========================================================================
extern "C" void kernel_launch(void* const* d_in, const int* in_sizes, int n_in,
                              void* d_out, int out_size) {
    const float* nodes = (const float*)d_in[0];
    const float* edges = (const float*)d_in[1];
    const float* aux   = (const float*)d_in[2];
    // d_in[3] = nums (unused)
    const float* Win   = (const float*)d_in[4];
    const float* b_in  = (const float*)d_in[5];
    const float* Wcoef = (const float*)d_in[6];
    const float* bcoef = (const float*)d_in[7];
    const float* Wout  = (const float*)d_in[8];
    const float* b_out = (const float*)d_in[9];

    float* out_nodes = (float*)d_out;                    // [4,256,256]
    float* out_cat   = out_nodes + (size_t)BIv * Dv;     // [4,256,256,256]

    cudaFuncSetAttribute(k_s12tc, cudaFuncAttributeMaxDynamicSharedMemorySize,
                         SMEM_S12_BYTES);
    cudaFuncSetAttribute(k_main, cudaFuncAttributeMaxDynamicSharedMemorySize,
                         SMEM_MAIN_BYTES);

    k_prep  <<<192, 256>>>(Win);
    k_s12tc <<<32, 256, SMEM_S12_BYTES>>>(nodes, b_in);
    k_main  <<<4096, 256, SMEM_MAIN_BYTES>>>(edges, Wcoef, aux, bcoef, out_cat);
    k_out   <<<dim3(32, 4), 256>>>(nodes, Wout, b_out, out_nodes);
}